// round 15
// baseline (speedup 1.0000x reference)
#include <cuda_runtime.h>
#include <cuda_bf16.h>
#include <cstdint>
#include <cstddef>

// MinimalRNN 3-layer tanh RNN, S=256, B=256, H=1024.
// Persistent kernel, skewed layer pipeline (layer l computes t = s - l).
// sm_103a pass: tcgen05 bf16 3-pass (hi/lo split), SS mode: A AND W staged
// into SMEM via cp.async (no registers, no STTM), control warp issues MMAs.
// Base sm_103 pass: SIMT fp32x2 fallback.
// R15: kill the register-mediated A path (512-cyc LDG issue + STTM + fences
// pinned every prior round at ~4500 cyc/chunk). SS @ M=128 has the same
// 32-cyc MMA floor as TS (SMEM penalty applies only at M=64).

#if defined(__CUDA_ARCH_FEAT_SM103_ALL) || defined(__CUDA_ARCH_FEAT_SM100_ALL) || \
    defined(__CUDA_ARCH_FEAT_SM101_ALL) || defined(__CUDA_ARCH_SPECIFIC__)
#define TC_OK 1
#endif
#if !defined(__CUDA_ARCH__) || defined(TC_OK)
#define COMPILE_TC 1          // host pass + arch-specific device pass
#endif

#define S_LEN   256
#define BATCH   256
#define HID     1024
#define NLAYER  3
#define NT      64
#define TPL     (HID / NT)          // 16
#define NCTA    (NLAYER * TPL)      // 48
#define NTHREADS 288                // 8 stager warps + 1 control warp
#define KC      64                  // k elems per chunk
#define NCHUNK  32                  // 2 GEMMs x 16 chunks
#define BH      ((size_t)BATCH * HID)
#define Y_ELEMS ((size_t)S_LEN * BATCH * HID)

// Stage slot layout (bytes): A hi 32K, A lo 32K, W hi 8K, W lo 8K
#define OFF_AHI 0
#define OFF_ALO 32768
#define OFF_WHI 65536
#define OFF_WLO 73728
#define SLOTSZ  81920
#define SMEM_DYN (2 * SLOTSZ + 1024)

// TMEM: D accumulator only (128 cols)
#define TM_D    0

// idesc kind::f16: dtype=F32(1<<4) atype=BF16(1<<7) btype=BF16(1<<10)
// N/8=8 (<<17), M/16=8 (<<24)
#define IDESC 0x08100490u

// ---------------- global scratch ----------------
__device__ __align__(16) __nv_bfloat16 g_w_hi[2u * NLAYER * HID * HID];
__device__ __align__(16) __nv_bfloat16 g_w_lo[2u * NLAYER * HID * HID];
__device__ __align__(16) __nv_bfloat16 g_x_hi[(size_t)S_LEN * BATCH * HID];
__device__ __align__(16) __nv_bfloat16 g_x_lo[(size_t)S_LEN * BATCH * HID];
__device__ __align__(16) __nv_bfloat16 g_h_hi[2][NLAYER][BATCH][HID];
__device__ __align__(16) __nv_bfloat16 g_h_lo[2][NLAYER][BATCH][HID];
__device__ __align__(16) float         g_hf[2][NLAYER][BATCH][HID];  // fallback
__device__ unsigned g_count = 0;
__device__ unsigned g_gen   = 0;

// ---------------- generic helpers ----------------
__device__ __forceinline__ uint32_t smem_u32(const void* p) {
    uint32_t a;
    asm("{ .reg .u64 t; cvta.to.shared.u64 t, %1; cvt.u32.u64 %0, t; }"
        : "=r"(a) : "l"(p));
    return a;
}
__device__ __forceinline__ uint32_t swz(uint32_t off) {   // SW128
    return off ^ ((off >> 3) & 0x70);
}
__device__ __forceinline__ uint64_t mkdesc(uint32_t addr) { // SW128, LBO=1, SBO=64
    return ((uint64_t)2 << 61) | ((uint64_t)1 << 46) | ((uint64_t)64 << 32)
         | ((uint64_t)1 << 16) | ((addr >> 4) & 0x3FFF);
}
__device__ __forceinline__ uint32_t pkbf(__nv_bfloat16 a, __nv_bfloat16 b) {
    __nv_bfloat162 t = __halves2bfloat162(a, b);
    return *reinterpret_cast<uint32_t*>(&t);
}
__device__ __forceinline__ void split2(float x, float y, uint32_t& h, uint32_t& l) {
    __nv_bfloat16 hx = __float2bfloat16(x), hy = __float2bfloat16(y);
    __nv_bfloat16 lx = __float2bfloat16(x - __bfloat162float(hx));
    __nv_bfloat16 ly = __float2bfloat16(y - __bfloat162float(hy));
    h = pkbf(hx, hy); l = pkbf(lx, ly);
}

// ---------------- grid barrier ----------------
__device__ __forceinline__ unsigned ld_acq(const unsigned* p) {
    unsigned v;
    asm volatile("ld.acquire.gpu.global.u32 %0, [%1];" : "=r"(v) : "l"(p) : "memory");
    return v;
}
__device__ __forceinline__ void grid_barrier() {
    __syncthreads();
    if (threadIdx.x == 0) {
        __threadfence();
        unsigned gen = ld_acq(&g_gen);
        __threadfence();
        unsigned ticket = atomicAdd(&g_count, 1u);
        if (ticket == NCTA - 1) {
            atomicExch(&g_count, 0u);
            __threadfence();
            atomicAdd(&g_gen, 1u);
        } else {
            while (ld_acq(&g_gen) == gen) { __nanosleep(64); }
        }
        __threadfence();
    }
    __syncthreads();
}

// ---------------- packed f32x2 (fallback path) ----------------
__device__ __forceinline__ void ffma2(unsigned long long& d,
                                      unsigned long long a, unsigned long long b) {
    asm volatile("fma.rn.f32x2 %0, %1, %2, %0;" : "+l"(d) : "l"(a), "l"(b));
}
__device__ __forceinline__ unsigned long long splat2(float v) {
    unsigned long long r;
    asm("mov.b64 %0, {%1, %1};" : "=l"(r) : "f"(v));
    return r;
}
__device__ __forceinline__ unsigned long long pack2(float a, float b) {
    unsigned long long r;
    asm("mov.b64 %0, {%1, %2};" : "=l"(r) : "f"(a), "f"(b));
    return r;
}
__device__ __forceinline__ float2 unpack2(unsigned long long v) {
    float2 f;
    asm("mov.b64 {%0, %1}, %2;" : "=f"(f.x), "=f"(f.y) : "l"(v));
    return f;
}

#define FB_KC   32
#define FB_ASTR 36
#define FB_WSTR 20
__device__ __forceinline__ void simt_gemm(
    const float* __restrict__ A, const float* __restrict__ W,
    int n0, int tid, int ty, int tx,
    unsigned long long acc[4][2],
    float (*At)[FB_ASTR], float (*Wt)[FB_WSTR])
{
    const int arow = tid >> 3, aq = tid & 7;
    const int wc = tid & 15, wq = tid >> 4;
    for (int kc = 0; kc < HID; kc += FB_KC) {
        if (tid < 256) {
            #pragma unroll
            for (int it = 0; it < 8; it++) {
                int row = arow + 32 * it;
                float4 v = __ldcg((const float4*)(A + (size_t)row * HID + kc + aq * 4));
                *(float4*)&At[row][aq * 4] = v;
            }
        }
        if (tid < 128) {
            float4 wv = __ldg((const float4*)(W + (size_t)(n0 + wc) * HID + kc + wq * 4));
            Wt[wq * 4 + 0][wc] = wv.x; Wt[wq * 4 + 1][wc] = wv.y;
            Wt[wq * 4 + 2][wc] = wv.z; Wt[wq * 4 + 3][wc] = wv.w;
        }
        __syncthreads();
        if (tid < 256) {
            #pragma unroll
            for (int k4 = 0; k4 < FB_KC; k4 += 4) {
                ulonglong2 wp[4];
                #pragma unroll
                for (int j = 0; j < 4; j++)
                    wp[j] = *(const ulonglong2*)&Wt[k4 + j][tx * 4];
                float4 av[4];
                #pragma unroll
                for (int ri = 0; ri < 4; ri++)
                    av[ri] = *(const float4*)&At[ty + 64 * ri][k4];
                #pragma unroll
                for (int j = 0; j < 4; j++) {
                    #pragma unroll
                    for (int ri = 0; ri < 4; ri++) {
                        unsigned long long as = splat2(((const float*)&av[ri])[j]);
                        ffma2(acc[ri][0], as, wp[j].x);
                        ffma2(acc[ri][1], as, wp[j].y);
                    }
                }
            }
        }
        __syncthreads();
    }
}

// ---------------- tcgen05 / async wrappers (arch-specific pass only) --------
#if defined(COMPILE_TC)
#define MBARRIER_INIT(addr, cnt) \
    asm volatile("mbarrier.init.shared.b64 [%0], %1;" :: "r"(addr), "r"(cnt) : "memory")
#define MBAR_ARRIVE(addr) \
    asm volatile("mbarrier.arrive.shared.b64 _, [%0];" :: "r"(addr) : "memory")
#define MBAR_WAIT(addr, parity) do {                                            \
    uint32_t _done;                                                             \
    asm volatile("{\n\t.reg .pred p;\n\t"                                       \
        "mbarrier.try_wait.parity.acquire.cta.shared::cta.b64 p, [%1], %2;\n\t" \
        "selp.b32 %0, 1, 0, p;\n\t}"                                            \
        : "=r"(_done) : "r"(addr), "r"(parity) : "memory");                     \
    if (!_done) {                                                               \
        asm volatile("{\n\t.reg .pred P1;\n\t"                                  \
            "WL_%=:\n\t"                                                        \
            "mbarrier.try_wait.parity.acquire.cta.shared::cta.b64 P1, [%0], %1, 0x989680;\n\t" \
            "@P1 bra.uni WD_%=;\n\t"                                            \
            "bra.uni WL_%=;\n\t"                                                \
            "WD_%=:\n\t}" :: "r"(addr), "r"(parity) : "memory");                \
    }                                                                           \
} while (0)

__device__ __forceinline__ void tc_alloc(uint32_t dst_smem, uint32_t ncols) {
    asm volatile("tcgen05.alloc.cta_group::1.sync.aligned.shared::cta.b32 [%0], %1;"
                 :: "r"(dst_smem), "r"(ncols) : "memory");
}
__device__ __forceinline__ void tc_dealloc(uint32_t tmem, uint32_t ncols) {
    asm volatile("tcgen05.dealloc.cta_group::1.sync.aligned.b32 %0, %1;"
                 :: "r"(tmem), "r"(ncols));
}
__device__ __forceinline__ void tc_relinquish() {
    asm volatile("tcgen05.relinquish_alloc_permit.cta_group::1.sync.aligned;");
}
// SS form: both operands via SMEM descriptors
__device__ __forceinline__ void tc_mma_ss(uint32_t d, uint64_t ad, uint64_t bd,
                                          uint32_t idesc, uint32_t en) {
    asm volatile("{\n\t.reg .pred p;\n\tsetp.ne.u32 p, %5, 0;\n\t"
        "tcgen05.mma.cta_group::1.kind::f16 [%0], %1, %2, %3, {%4,%4,%4,%4}, p;\n\t}"
        :: "r"(d), "l"(ad), "l"(bd), "r"(idesc), "r"(0u), "r"(en) : "memory");
}
__device__ __forceinline__ void tc_commit(uint32_t mbar) {
    asm volatile("tcgen05.commit.cta_group::1.mbarrier::arrive::one.shared::cluster.b64 [%0];"
                 :: "r"(mbar) : "memory");
}
#define TC_FENCE_BEFORE() asm volatile("tcgen05.fence::before_thread_sync;" ::: "memory")
#define TC_FENCE_AFTER()  asm volatile("tcgen05.fence::after_thread_sync;"  ::: "memory")
#define TC_WAIT_LD()      asm volatile("tcgen05.wait::ld.sync.aligned;" ::: "memory")
#define FENCE_ASYNC()     asm volatile("fence.proxy.async.shared::cta;" ::: "memory")

// cp.async 16B global->shared (LDGSTS), bypasses registers
__device__ __forceinline__ void cp16(uint32_t dst, const void* src) {
    asm volatile("cp.async.cg.shared.global [%0], [%1], 16;"
                 :: "r"(dst), "l"(src) : "memory");
}
#define CP_COMMIT() asm volatile("cp.async.commit_group;" ::: "memory")
#define CP_WAIT1()  asm volatile("cp.async.wait_group 1;" ::: "memory")

#define LDTM_X32(r, a)                                                          \
    asm volatile("tcgen05.ld.sync.aligned.32x32b.x32.b32 "                      \
        "{%0,%1,%2,%3,%4,%5,%6,%7,%8,%9,%10,%11,%12,%13,%14,%15,"               \
        "%16,%17,%18,%19,%20,%21,%22,%23,%24,%25,%26,%27,%28,%29,%30,%31}, [%32];" \
        : "=r"((r)[0]),"=r"((r)[1]),"=r"((r)[2]),"=r"((r)[3]),                  \
          "=r"((r)[4]),"=r"((r)[5]),"=r"((r)[6]),"=r"((r)[7]),                  \
          "=r"((r)[8]),"=r"((r)[9]),"=r"((r)[10]),"=r"((r)[11]),                \
          "=r"((r)[12]),"=r"((r)[13]),"=r"((r)[14]),"=r"((r)[15]),              \
          "=r"((r)[16]),"=r"((r)[17]),"=r"((r)[18]),"=r"((r)[19]),              \
          "=r"((r)[20]),"=r"((r)[21]),"=r"((r)[22]),"=r"((r)[23]),              \
          "=r"((r)[24]),"=r"((r)[25]),"=r"((r)[26]),"=r"((r)[27]),              \
          "=r"((r)[28]),"=r"((r)[29]),"=r"((r)[30]),"=r"((r)[31])               \
        : "r"(a))
#endif // COMPILE_TC

// ---------------- prelude kernels ----------------
extern "C" __global__ void split_weights(const float* __restrict__ Wih,
                                         const float* __restrict__ Whh) {
    size_t tot4 = (size_t)NLAYER * HID * HID / 4;
    size_t i4 = (size_t)blockIdx.x * blockDim.x + threadIdx.x;
    if (i4 >= tot4) return;
    float4 a = __ldg((const float4*)Wih + i4);
    float4 b = __ldg((const float4*)Whh + i4);
    uint2 h, l;
    split2(a.x, a.y, h.x, l.x); split2(a.z, a.w, h.y, l.y);
    ((uint2*)g_w_hi)[i4] = h;  ((uint2*)g_w_lo)[i4] = l;
    split2(b.x, b.y, h.x, l.x); split2(b.z, b.w, h.y, l.y);
    ((uint2*)g_w_hi)[tot4 + i4] = h;  ((uint2*)g_w_lo)[tot4 + i4] = l;
}

extern "C" __global__ void split_x(const float* __restrict__ x) {
    size_t tot4 = Y_ELEMS / 4;
    for (size_t i4 = (size_t)blockIdx.x * blockDim.x + threadIdx.x;
         i4 < tot4; i4 += (size_t)gridDim.x * blockDim.x) {
        float4 a = __ldg((const float4*)x + i4);
        uint2 h, l;
        split2(a.x, a.y, h.x, l.x); split2(a.z, a.w, h.y, l.y);
        ((uint2*)g_x_hi)[i4] = h;  ((uint2*)g_x_lo)[i4] = l;
    }
}

// seed h0 into the parity slot read at t==0 for each layer: pp = (l+1)&1
extern "C" __global__ void seed_h0(const float* __restrict__ h0) {
    size_t tot4 = (size_t)NLAYER * BH / 4;
    size_t i4 = (size_t)blockIdx.x * blockDim.x + threadIdx.x;
    if (i4 >= tot4) return;
    int l = (int)(i4 / (BH / 4));
    size_t r4 = i4 % (BH / 4);
    int pp = (l + 1) & 1;
    float4 a = __ldg((const float4*)h0 + i4);
    uint2 h, lo;
    split2(a.x, a.y, h.x, lo.x); split2(a.z, a.w, h.y, lo.y);
    ((uint2*)&g_h_hi[pp][l][0][0])[r4] = h;
    ((uint2*)&g_h_lo[pp][l][0][0])[r4] = lo;
}

#if defined(COMPILE_TC)
// ---------------- chunk fetch via cp.async: A (16 cp16) + W (4 cp16) ------
__device__ __forceinline__ void cpChunk(
    int ch, int tid, int l, int n0, uint32_t bb,
    const __nv_bfloat16* a0h, const __nv_bfloat16* a0l,
    const __nv_bfloat16* a1h, const __nv_bfloat16* a1l)
{
    const int g  = ch >> 4;
    const int k0 = (ch & 15) * KC;
    // A: row = tid, 128 bytes hi + 128 bytes lo
    {
        const __nv_bfloat16* sh = (g ? a1h : a0h) + (size_t)tid * HID + k0;
        const __nv_bfloat16* sl = (g ? a1l : a0l) + (size_t)tid * HID + k0;
        const uint32_t rb = (uint32_t)tid * 128u;
        #pragma unroll
        for (int q = 0; q < 8; q++) {
            uint32_t so = swz(rb + q * 16u);
            cp16(bb + OFF_AHI + so, sh + q * 8);
            cp16(bb + OFF_ALO + so, sl + q * 8);
        }
    }
    // W: row = tid>>2, 2x16B per hi/lo part
    {
        const int wrow = tid >> 2, qq = tid & 3;
        const size_t wbase = (((size_t)g * NLAYER + l) * HID + (n0 + wrow)) * HID + k0;
        #pragma unroll
        for (int e = 0; e < 2; e++) {
            int q = qq * 2 + e;
            uint32_t so = swz((uint32_t)wrow * 128u + (uint32_t)q * 16u);
            cp16(bb + OFF_WHI + so, g_w_hi + wbase + q * 8);
            cp16(bb + OFF_WLO + so, g_w_lo + wbase + q * 8);
        }
    }
}
#endif // COMPILE_TC

// ---------------- persistent RNN kernel ----------------
extern "C" __global__ void __launch_bounds__(NTHREADS, 1)
rnn_tc(const float* __restrict__ x,    // [S][B][H]
       const float* __restrict__ h0,   // [L][B][H]
       const float* __restrict__ Wih,  // fallback path only
       const float* __restrict__ Whh,  // fallback path only
       const float* __restrict__ bih,  // [L][H]
       const float* __restrict__ bhh,  // [L][H]
       float* __restrict__ out)        // y [S*B*H] ++ h_N [L*B*H]
{
#if defined(COMPILE_TC)
    // ================= tcgen05 SS-mode warp-specialized path =================
    (void)x; (void)h0; (void)Wih; (void)Whh;
    extern __shared__ __align__(1024) char dynsm[];
    __shared__ __align__(16) uint64_t cmbar[2];   // MMA commit per slot
    __shared__ __align__(16) uint64_t fmbar[2];   // staged (full) per slot
    __shared__ uint32_t tmem_ptr_sm;
    __shared__ float bias_sm[NT];

    const int tid  = threadIdx.x;
    const int wid  = tid >> 5;
    const int lane = tid & 31;
    const int l    = blockIdx.x / TPL;
    const int n0   = (blockIdx.x % TPL) * NT;
    const bool ctrl = (wid == 8);

    uint32_t smb = smem_u32(dynsm);
    smb = (smb + 1023u) & ~1023u;                 // slot ring base
    const uint32_t cm0 = smem_u32(&cmbar[0]);
    const uint32_t fm0 = smem_u32(&fmbar[0]);

    if (wid == 0) tc_alloc(smem_u32(&tmem_ptr_sm), 512);
    if (tid == 0) {
        MBARRIER_INIT(cm0 + 0, 1);  MBARRIER_INIT(cm0 + 8, 1);
        MBARRIER_INIT(fm0 + 0, 8);  MBARRIER_INIT(fm0 + 8, 8);
    }
    if (tid < NT)
        bias_sm[tid] = __ldg(&bih[l * HID + n0 + tid]) + __ldg(&bhh[l * HID + n0 + tid]);
    __syncthreads();
    const uint32_t tmem = tmem_ptr_sm;
    if (wid == 0) tc_relinquish();

    // per-slot phase counters (count consumed phases; persist across steps)
    unsigned sc0 = 0, sc1 = 0;     // stager: commit phases consumed
    unsigned fc0 = 0, fc1 = 0;     // control: full phases consumed

    for (int s = 0; s < S_LEN + NLAYER - 1; s++) {
        if (s > 0) grid_barrier();
        const int t = s - l;
        if (t < 0 || t >= S_LEN) continue;
        const int pp = (s + 1) & 1;

        const __nv_bfloat16* a0h = (l == 0) ? (g_x_hi + (size_t)t * BH)
                                            : &g_h_hi[pp][l - 1][0][0];
        const __nv_bfloat16* a0l = (l == 0) ? (g_x_lo + (size_t)t * BH)
                                            : &g_h_lo[pp][l - 1][0][0];
        const __nv_bfloat16* a1h = &g_h_hi[pp][l][0][0];
        const __nv_bfloat16* a1l = &g_h_lo[pp][l][0][0];

        if (!ctrl) {
            // ================== STAGER WARPS (0-7): cp.async producer =====
            // iter j stages chunk j; signals full(j-2); guards slot reuse
            // by waiting commit(j-2) BEFORE issuing cp(j) (j>=2).
            #pragma unroll 1
            for (int j = 0; j < NCHUNK + 2; j++) {
                if (j >= 2) {
                    CP_WAIT1();                  // cp group (j-2) complete
                    FENCE_ASYNC();
                    if (lane == 0)
                        MBAR_ARRIVE(((j - 2) & 1) ? fm0 + 8 : fm0 + 0);
                }
                if (j < NCHUNK) {
                    if (j >= 2) {                // slot (j&1): wait MMAs of j-2
                        if ((j & 1) == 0) { MBAR_WAIT(cm0 + 0, sc0 & 1); sc0++; }
                        else              { MBAR_WAIT(cm0 + 8, sc1 & 1); sc1++; }
                    }
                    cpChunk(j, tid, l, n0, smb + (uint32_t)(j & 1) * SLOTSZ,
                            a0h, a0l, a1h, a1l);
                }
                CP_COMMIT();                     // empty group for j>=NCHUNK
            }
            // final commits (chunks 30, 31 = phase 15 per slot)
            MBAR_WAIT(cm0 + 0, sc0 & 1); sc0++;
            MBAR_WAIT(cm0 + 8, sc1 & 1); sc1++;
            TC_FENCE_AFTER();
        } else {
            // ================== CONTROL WARP (8): MMA issuer ==============
            #pragma unroll 1
            for (int ch = 0; ch < NCHUNK; ch++) {
                const int b = ch & 1;
                if (b == 0) { MBAR_WAIT(fm0 + 0, fc0 & 1); fc0++; }
                else        { MBAR_WAIT(fm0 + 8, fc1 & 1); fc1++; }
                TC_FENCE_AFTER();
                if (lane == 0) {
                    const uint32_t bb = smb + (uint32_t)b * SLOTSZ;
                    #pragma unroll
                    for (int mh = 0; mh < 2; mh++) {
                        #pragma unroll
                        for (int ps = 0; ps < 3; ps++) {
                            // ps0: Ahi*Whi  ps1: Ahi*Wlo  ps2: Alo*Whi
                            uint64_t ad = mkdesc(bb + (ps == 2 ? OFF_ALO : OFF_AHI)
                                                 + (uint32_t)mh * 16384u);
                            uint64_t bd = mkdesc(bb + (ps == 1 ? OFF_WLO : OFF_WHI));
                            #pragma unroll
                            for (int ks = 0; ks < 4; ks++) {
                                uint32_t en = !(ch == 0 && ps == 0 && ks == 0);
                                tc_mma_ss(tmem + TM_D + mh * 64, ad + ks * 2,
                                          bd + ks * 2, IDESC, en);
                            }
                        }
                    }
                    tc_commit(b == 0 ? cm0 : cm0 + 8);
                }
            }
        }

        // ---- epilogue (stager warps only): LDTM -> +bias -> tanh -> store ----
        if (!ctrl) {
            const int mh  = wid >> 2;
            const int row = mh * 128 + (wid & 3) * 32 + lane;
            const int wp  = s & 1;

            #pragma unroll
            for (int hf = 0; hf < 2; hf++) {
                uint32_t r[32];
                LDTM_X32(r, tmem + TM_D + mh * 64 + hf * 32);
                TC_WAIT_LD();

                float hv[32];
                #pragma unroll
                for (int c = 0; c < 32; c++)
                    hv[c] = tanhf(__uint_as_float(r[c]) + bias_sm[hf * 32 + c]);

                uint32_t hip[16], lop[16];
                #pragma unroll
                for (int c = 0; c < 32; c += 2)
                    split2(hv[c], hv[c + 1], hip[c >> 1], lop[c >> 1]);

                uint4* dh = (uint4*)&g_h_hi[wp][l][row][n0 + hf * 32];
                uint4* dl = (uint4*)&g_h_lo[wp][l][row][n0 + hf * 32];
                #pragma unroll
                for (int q = 0; q < 4; q++) {
                    dh[q] = make_uint4(hip[4*q], hip[4*q+1], hip[4*q+2], hip[4*q+3]);
                    dl[q] = make_uint4(lop[4*q], lop[4*q+1], lop[4*q+2], lop[4*q+3]);
                }
                if (l == NLAYER - 1) {
                    float4* yb = (float4*)(out + (size_t)t * BH
                                           + (size_t)row * HID + n0 + hf * 32);
                    #pragma unroll
                    for (int q = 0; q < 8; q++)
                        yb[q] = make_float4(hv[4*q], hv[4*q+1], hv[4*q+2], hv[4*q+3]);
                }
                if (t == S_LEN - 1) {
                    float4* hb = (float4*)(out + Y_ELEMS + (size_t)l * BH
                                           + (size_t)row * HID + n0 + hf * 32);
                    #pragma unroll
                    for (int q = 0; q < 8; q++)
                        hb[q] = make_float4(hv[4*q], hv[4*q+1], hv[4*q+2], hv[4*q+3]);
                }
            }
            TC_FENCE_BEFORE();
        }
    }

    __syncthreads();
    if (wid == 0) tc_dealloc(tmem, 512);

#else
    // ================= SIMT fp32x2 fallback (base sm_103 pass) =================
    extern __shared__ __align__(16) char dynsm[];
    float (*At)[FB_ASTR] = (float(*)[FB_ASTR])dynsm;
    float (*Wt)[FB_WSTR] = (float(*)[FB_WSTR])(dynsm + sizeof(float) * BATCH * FB_ASTR);

    const int tid = threadIdx.x;
    const int ty  = tid >> 2;
    const int tx  = tid & 3;
    const int l   = blockIdx.x / TPL;
    const int nb  = (blockIdx.x % TPL) * NT;

    const float* Wl_ih = Wih + (size_t)l * HID * HID;
    const float* Wl_hh = Whh + (size_t)l * HID * HID;

    for (int s = 0; s < S_LEN + NLAYER - 1; s++) {
        if (s > 0) grid_barrier();
        int t = s - l;
        if (t < 0 || t >= S_LEN) continue;

        const float* A0 = (l == 0) ? (x + (size_t)t * BH) : &g_hf[(s + 1) & 1][l - 1][0][0];
        const float* A1 = (t == 0) ? (h0 + (size_t)l * BH) : &g_hf[(s + 1) & 1][l][0][0];

        for (int st = 0; st < NT / 16; st++) {
            const int n0 = nb + st * 16;
            float bias[4];
            #pragma unroll
            for (int j = 0; j < 4; j++) {
                int c = n0 + tx * 4 + j;
                bias[j] = __ldg(&bih[l * HID + c]) + __ldg(&bhh[l * HID + c]);
            }
            unsigned long long acc[4][2];
            #pragma unroll
            for (int ri = 0; ri < 4; ri++) {
                acc[ri][0] = pack2(bias[0], bias[1]);
                acc[ri][1] = pack2(bias[2], bias[3]);
            }
            simt_gemm(A0, Wl_ih, n0, tid, ty, tx, acc, At, Wt);
            simt_gemm(A1, Wl_hh, n0, tid, ty, tx, acc, At, Wt);

            if (tid < 256) {
                float* hb = &g_hf[s & 1][l][0][0];
                #pragma unroll
                for (int ri = 0; ri < 4; ri++) {
                    float2 v0 = unpack2(acc[ri][0]);
                    float2 v1 = unpack2(acc[ri][1]);
                    float4 h;
                    h.x = tanhf(v0.x); h.y = tanhf(v0.y);
                    h.z = tanhf(v1.x); h.w = tanhf(v1.y);
                    int row = ty + 64 * ri;
                    size_t off = (size_t)row * HID + n0 + tx * 4;
                    *(float4*)(hb + off) = h;
                    if (l == NLAYER - 1)
                        *(float4*)(out + (size_t)t * BH + off) = h;
                    if (t == S_LEN - 1)
                        *(float4*)(out + Y_ELEMS + (size_t)l * BH + off) = h;
                }
            }
        }
    }
#endif
}

extern "C" void kernel_launch(void* const* d_in, const int* in_sizes, int n_in,
                              void* d_out, int out_size) {
    const float* x   = (const float*)d_in[0];
    const float* h0  = (const float*)d_in[1];
    const float* Wih = (const float*)d_in[2];
    const float* Whh = (const float*)d_in[3];
    const float* bih = (const float*)d_in[4];
    const float* bhh = (const float*)d_in[5];

    cudaFuncSetAttribute(rnn_tc, cudaFuncAttributeMaxDynamicSharedMemorySize, SMEM_DYN);

    size_t tot4 = (size_t)NLAYER * HID * HID / 4;
    split_weights<<<(unsigned)((tot4 + 255) / 256), 256>>>(Wih, Whh);
    split_x<<<4096, 256>>>(x);
    size_t h4 = (size_t)NLAYER * BH / 4;
    seed_h0<<<(unsigned)((h4 + 255) / 256), 256>>>(h0);
    rnn_tc<<<NCTA, NTHREADS, SMEM_DYN>>>(x, h0, Wih, Whh, bih, bhh, (float*)d_out);
}

// round 16
// speedup vs baseline: 1.9069x; 1.9069x over previous
#include <cuda_runtime.h>
#include <cuda.h>
#include <cuda_bf16.h>
#include <cstdint>
#include <cstddef>

// MinimalRNN 3-layer tanh RNN, S=256, B=256, H=1024.
// Persistent kernel, skewed layer pipeline (layer l computes t = s - l).
// sm_103a pass: tcgen05 bf16 3-pass (hi/lo split), SS mode; operands staged
// by TMA (UTMALDG, SW128) with expect_tx mbarriers; dedicated producer and
// issuer warps; warps 0-7 do the epilogue. Base pass: SIMT fp32x2 fallback.
// R16: replace ALL per-thread staging (LDG/STTM/cp.async + per-chunk fences,
// invariant ~4500 cyc/chunk across R9-R15) with 4 TMA loads per chunk.

#if defined(__CUDA_ARCH_FEAT_SM103_ALL) || defined(__CUDA_ARCH_FEAT_SM100_ALL) || \
    defined(__CUDA_ARCH_FEAT_SM101_ALL) || defined(__CUDA_ARCH_SPECIFIC__)
#define TC_OK 1
#endif
#if !defined(__CUDA_ARCH__) || defined(TC_OK)
#define COMPILE_TC 1          // host pass + arch-specific device pass
#endif

#define S_LEN   256
#define BATCH   256
#define HID     1024
#define NLAYER  3
#define NT      64
#define TPL     (HID / NT)          // 16
#define NCTA    (NLAYER * TPL)      // 48
#define NTHREADS 320                // 8 epilogue warps + producer + issuer
#define KC      64                  // k elems per chunk
#define NCHUNK  32                  // 2 GEMMs x 16 chunks
#define BH      ((size_t)BATCH * HID)
#define Y_ELEMS ((size_t)S_LEN * BATCH * HID)

// Stage slot layout (bytes): A hi 32K, A lo 32K, W hi 8K, W lo 8K
#define OFF_AHI 0
#define OFF_ALO 32768
#define OFF_WHI 65536
#define OFF_WLO 73728
#define SLOTSZ  81920
#define SMEM_DYN (2 * SLOTSZ + 1024)

#define TM_D    0                   // TMEM: D accumulator only (128 cols)

// idesc kind::f16: dtype=F32(1<<4) atype=BF16(1<<7) btype=BF16(1<<10)
// N/8=8 (<<17), M/16=8 (<<24)
#define IDESC 0x08100490u

// ---------------- global scratch ----------------
__device__ __align__(16) __nv_bfloat16 g_w_hi[2u * NLAYER * HID * HID];
__device__ __align__(16) __nv_bfloat16 g_w_lo[2u * NLAYER * HID * HID];
__device__ __align__(16) __nv_bfloat16 g_x_hi[(size_t)S_LEN * BATCH * HID];
__device__ __align__(16) __nv_bfloat16 g_x_lo[(size_t)S_LEN * BATCH * HID];
__device__ __align__(16) __nv_bfloat16 g_h_hi[2][NLAYER][BATCH][HID];
__device__ __align__(16) __nv_bfloat16 g_h_lo[2][NLAYER][BATCH][HID];
__device__ __align__(16) float         g_hf[2][NLAYER][BATCH][HID];  // fallback
__device__ unsigned g_count = 0;
__device__ unsigned g_gen   = 0;

// ---------------- generic helpers ----------------
__device__ __forceinline__ uint32_t smem_u32(const void* p) {
    uint32_t a;
    asm("{ .reg .u64 t; cvta.to.shared.u64 t, %1; cvt.u32.u64 %0, t; }"
        : "=r"(a) : "l"(p));
    return a;
}
__device__ __forceinline__ uint64_t mkdesc(uint32_t addr) { // SW128, LBO=1, SBO=64
    return ((uint64_t)2 << 61) | ((uint64_t)1 << 46) | ((uint64_t)64 << 32)
         | ((uint64_t)1 << 16) | ((addr >> 4) & 0x3FFF);
}
__device__ __forceinline__ uint32_t pkbf(__nv_bfloat16 a, __nv_bfloat16 b) {
    __nv_bfloat162 t = __halves2bfloat162(a, b);
    return *reinterpret_cast<uint32_t*>(&t);
}
__device__ __forceinline__ void split2(float x, float y, uint32_t& h, uint32_t& l) {
    __nv_bfloat16 hx = __float2bfloat16(x), hy = __float2bfloat16(y);
    __nv_bfloat16 lx = __float2bfloat16(x - __bfloat162float(hx));
    __nv_bfloat16 ly = __float2bfloat16(y - __bfloat162float(hy));
    h = pkbf(hx, hy); l = pkbf(lx, ly);
}

// ---------------- grid barrier ----------------
__device__ __forceinline__ unsigned ld_acq(const unsigned* p) {
    unsigned v;
    asm volatile("ld.acquire.gpu.global.u32 %0, [%1];" : "=r"(v) : "l"(p) : "memory");
    return v;
}
__device__ __forceinline__ void grid_barrier() {
    __syncthreads();
    if (threadIdx.x == 0) {
        __threadfence();
        unsigned gen = ld_acq(&g_gen);
        __threadfence();
        unsigned ticket = atomicAdd(&g_count, 1u);
        if (ticket == NCTA - 1) {
            atomicExch(&g_count, 0u);
            __threadfence();
            atomicAdd(&g_gen, 1u);
        } else {
            while (ld_acq(&g_gen) == gen) { __nanosleep(64); }
        }
        __threadfence();
    }
    __syncthreads();
}

// ---------------- packed f32x2 (fallback path) ----------------
__device__ __forceinline__ void ffma2(unsigned long long& d,
                                      unsigned long long a, unsigned long long b) {
    asm volatile("fma.rn.f32x2 %0, %1, %2, %0;" : "+l"(d) : "l"(a), "l"(b));
}
__device__ __forceinline__ unsigned long long splat2(float v) {
    unsigned long long r;
    asm("mov.b64 %0, {%1, %1};" : "=l"(r) : "f"(v));
    return r;
}
__device__ __forceinline__ unsigned long long pack2(float a, float b) {
    unsigned long long r;
    asm("mov.b64 %0, {%1, %2};" : "=l"(r) : "f"(a), "f"(b));
    return r;
}
__device__ __forceinline__ float2 unpack2(unsigned long long v) {
    float2 f;
    asm("mov.b64 {%0, %1}, %2;" : "=f"(f.x), "=f"(f.y) : "l"(v));
    return f;
}

#define FB_KC   32
#define FB_ASTR 36
#define FB_WSTR 20
__device__ __forceinline__ void simt_gemm(
    const float* __restrict__ A, const float* __restrict__ W,
    int n0, int tid, int ty, int tx,
    unsigned long long acc[4][2],
    float (*At)[FB_ASTR], float (*Wt)[FB_WSTR])
{
    const int arow = tid >> 3, aq = tid & 7;
    const int wc = tid & 15, wq = tid >> 4;
    for (int kc = 0; kc < HID; kc += FB_KC) {
        if (tid < 256) {
            #pragma unroll
            for (int it = 0; it < 8; it++) {
                int row = arow + 32 * it;
                float4 v = __ldcg((const float4*)(A + (size_t)row * HID + kc + aq * 4));
                *(float4*)&At[row][aq * 4] = v;
            }
        }
        if (tid < 128) {
            float4 wv = __ldg((const float4*)(W + (size_t)(n0 + wc) * HID + kc + wq * 4));
            Wt[wq * 4 + 0][wc] = wv.x; Wt[wq * 4 + 1][wc] = wv.y;
            Wt[wq * 4 + 2][wc] = wv.z; Wt[wq * 4 + 3][wc] = wv.w;
        }
        __syncthreads();
        if (tid < 256) {
            #pragma unroll
            for (int k4 = 0; k4 < FB_KC; k4 += 4) {
                ulonglong2 wp[4];
                #pragma unroll
                for (int j = 0; j < 4; j++)
                    wp[j] = *(const ulonglong2*)&Wt[k4 + j][tx * 4];
                float4 av[4];
                #pragma unroll
                for (int ri = 0; ri < 4; ri++)
                    av[ri] = *(const float4*)&At[ty + 64 * ri][k4];
                #pragma unroll
                for (int j = 0; j < 4; j++) {
                    #pragma unroll
                    for (int ri = 0; ri < 4; ri++) {
                        unsigned long long as = splat2(((const float*)&av[ri])[j]);
                        ffma2(acc[ri][0], as, wp[j].x);
                        ffma2(acc[ri][1], as, wp[j].y);
                    }
                }
            }
        }
        __syncthreads();
    }
}

// ---------------- tcgen05 / TMA wrappers (arch-specific pass only) ----------
#if defined(COMPILE_TC)
#define MBARRIER_INIT(addr, cnt) \
    asm volatile("mbarrier.init.shared.b64 [%0], %1;" :: "r"(addr), "r"(cnt) : "memory")
#define MBARRIER_EXPECT_TX(addr, bytes) \
    asm volatile("mbarrier.arrive.expect_tx.shared.b64 _, [%0], %1;" \
                 :: "r"(addr), "r"(bytes) : "memory")
#define MBAR_WAIT(addr, parity) do {                                            \
    uint32_t _done;                                                             \
    asm volatile("{\n\t.reg .pred p;\n\t"                                       \
        "mbarrier.try_wait.parity.acquire.cta.shared::cta.b64 p, [%1], %2;\n\t" \
        "selp.b32 %0, 1, 0, p;\n\t}"                                            \
        : "=r"(_done) : "r"(addr), "r"(parity) : "memory");                     \
    if (!_done) {                                                               \
        asm volatile("{\n\t.reg .pred P1;\n\t"                                  \
            "WL_%=:\n\t"                                                        \
            "mbarrier.try_wait.parity.acquire.cta.shared::cta.b64 P1, [%0], %1, 0x989680;\n\t" \
            "@P1 bra.uni WD_%=;\n\t"                                            \
            "bra.uni WL_%=;\n\t"                                                \
            "WD_%=:\n\t}" :: "r"(addr), "r"(parity) : "memory");                \
    }                                                                           \
} while (0)

#define TMA_LOAD_2D(smem, map, cx, cy, mbar)                                    \
    asm volatile("cp.async.bulk.tensor.2d.shared::cta.global.tile"              \
        ".mbarrier::complete_tx::bytes [%0], [%1, {%2, %3}], [%4];"             \
        :: "r"(smem), "l"(map), "r"(cx), "r"(cy), "r"(mbar) : "memory")

__device__ __forceinline__ void tc_alloc(uint32_t dst_smem, uint32_t ncols) {
    asm volatile("tcgen05.alloc.cta_group::1.sync.aligned.shared::cta.b32 [%0], %1;"
                 :: "r"(dst_smem), "r"(ncols) : "memory");
}
__device__ __forceinline__ void tc_dealloc(uint32_t tmem, uint32_t ncols) {
    asm volatile("tcgen05.dealloc.cta_group::1.sync.aligned.b32 %0, %1;"
                 :: "r"(tmem), "r"(ncols));
}
__device__ __forceinline__ void tc_relinquish() {
    asm volatile("tcgen05.relinquish_alloc_permit.cta_group::1.sync.aligned;");
}
__device__ __forceinline__ void tc_mma_ss(uint32_t d, uint64_t ad, uint64_t bd,
                                          uint32_t idesc, uint32_t en) {
    asm volatile("{\n\t.reg .pred p;\n\tsetp.ne.u32 p, %5, 0;\n\t"
        "tcgen05.mma.cta_group::1.kind::f16 [%0], %1, %2, %3, {%4,%4,%4,%4}, p;\n\t}"
        :: "r"(d), "l"(ad), "l"(bd), "r"(idesc), "r"(0u), "r"(en) : "memory");
}
__device__ __forceinline__ void tc_commit(uint32_t mbar) {
    asm volatile("tcgen05.commit.cta_group::1.mbarrier::arrive::one.shared::cluster.b64 [%0];"
                 :: "r"(mbar) : "memory");
}
#define TC_FENCE_BEFORE() asm volatile("tcgen05.fence::before_thread_sync;" ::: "memory")
#define TC_FENCE_AFTER()  asm volatile("tcgen05.fence::after_thread_sync;"  ::: "memory")
#define TC_WAIT_LD()      asm volatile("tcgen05.wait::ld.sync.aligned;" ::: "memory")

#define LDTM_X32(r, a)                                                          \
    asm volatile("tcgen05.ld.sync.aligned.32x32b.x32.b32 "                      \
        "{%0,%1,%2,%3,%4,%5,%6,%7,%8,%9,%10,%11,%12,%13,%14,%15,"               \
        "%16,%17,%18,%19,%20,%21,%22,%23,%24,%25,%26,%27,%28,%29,%30,%31}, [%32];" \
        : "=r"((r)[0]),"=r"((r)[1]),"=r"((r)[2]),"=r"((r)[3]),                  \
          "=r"((r)[4]),"=r"((r)[5]),"=r"((r)[6]),"=r"((r)[7]),                  \
          "=r"((r)[8]),"=r"((r)[9]),"=r"((r)[10]),"=r"((r)[11]),                \
          "=r"((r)[12]),"=r"((r)[13]),"=r"((r)[14]),"=r"((r)[15]),              \
          "=r"((r)[16]),"=r"((r)[17]),"=r"((r)[18]),"=r"((r)[19]),              \
          "=r"((r)[20]),"=r"((r)[21]),"=r"((r)[22]),"=r"((r)[23]),              \
          "=r"((r)[24]),"=r"((r)[25]),"=r"((r)[26]),"=r"((r)[27]),              \
          "=r"((r)[28]),"=r"((r)[29]),"=r"((r)[30]),"=r"((r)[31])               \
        : "r"(a))
#endif // COMPILE_TC

// ---------------- prelude kernels ----------------
extern "C" __global__ void split_weights(const float* __restrict__ Wih,
                                         const float* __restrict__ Whh) {
    size_t tot4 = (size_t)NLAYER * HID * HID / 4;
    size_t i4 = (size_t)blockIdx.x * blockDim.x + threadIdx.x;
    if (i4 >= tot4) return;
    float4 a = __ldg((const float4*)Wih + i4);
    float4 b = __ldg((const float4*)Whh + i4);
    uint2 h, l;
    split2(a.x, a.y, h.x, l.x); split2(a.z, a.w, h.y, l.y);
    ((uint2*)g_w_hi)[i4] = h;  ((uint2*)g_w_lo)[i4] = l;
    split2(b.x, b.y, h.x, l.x); split2(b.z, b.w, h.y, l.y);
    ((uint2*)g_w_hi)[tot4 + i4] = h;  ((uint2*)g_w_lo)[tot4 + i4] = l;
}

extern "C" __global__ void split_x(const float* __restrict__ x) {
    size_t tot4 = Y_ELEMS / 4;
    for (size_t i4 = (size_t)blockIdx.x * blockDim.x + threadIdx.x;
         i4 < tot4; i4 += (size_t)gridDim.x * blockDim.x) {
        float4 a = __ldg((const float4*)x + i4);
        uint2 h, l;
        split2(a.x, a.y, h.x, l.x); split2(a.z, a.w, h.y, l.y);
        ((uint2*)g_x_hi)[i4] = h;  ((uint2*)g_x_lo)[i4] = l;
    }
}

// seed h0 into the parity slot read at t==0 for each layer: pp = (l+1)&1
extern "C" __global__ void seed_h0(const float* __restrict__ h0) {
    size_t tot4 = (size_t)NLAYER * BH / 4;
    size_t i4 = (size_t)blockIdx.x * blockDim.x + threadIdx.x;
    if (i4 >= tot4) return;
    int l = (int)(i4 / (BH / 4));
    size_t r4 = i4 % (BH / 4);
    int pp = (l + 1) & 1;
    float4 a = __ldg((const float4*)h0 + i4);
    uint2 h, lo;
    split2(a.x, a.y, h.x, lo.x); split2(a.z, a.w, h.y, lo.y);
    ((uint2*)&g_h_hi[pp][l][0][0])[r4] = h;
    ((uint2*)&g_h_lo[pp][l][0][0])[r4] = lo;
}

// ---------------- persistent RNN kernel ----------------
extern "C" __global__ void __launch_bounds__(NTHREADS, 1)
rnn_tc(const __grid_constant__ CUtensorMap mxh,  // g_x_hi  [65536 x 1024]
       const __grid_constant__ CUtensorMap mxl,  // g_x_lo
       const __grid_constant__ CUtensorMap mhh,  // g_h_hi  [1536 x 1024]
       const __grid_constant__ CUtensorMap mhl,  // g_h_lo
       const __grid_constant__ CUtensorMap mwh,  // g_w_hi  [6144 x 1024]
       const __grid_constant__ CUtensorMap mwl,  // g_w_lo
       const float* __restrict__ x,    // fallback only
       const float* __restrict__ h0,   // fallback only
       const float* __restrict__ Wih,  // fallback only
       const float* __restrict__ Whh,  // fallback only
       const float* __restrict__ bih,  // [L][H]
       const float* __restrict__ bhh,  // [L][H]
       float* __restrict__ out)        // y [S*B*H] ++ h_N [L*B*H]
{
#if defined(COMPILE_TC)
    // ================= tcgen05 SS + TMA warp-specialized path ==============
    (void)x; (void)h0; (void)Wih; (void)Whh;
    extern __shared__ __align__(1024) char dynsm[];
    __shared__ __align__(16) uint64_t cmbar[2];   // MMA commit per slot
    __shared__ __align__(16) uint64_t fmbar[2];   // TMA full per slot
    __shared__ uint32_t tmem_ptr_sm;
    __shared__ float bias_sm[NT];

    const int tid  = threadIdx.x;
    const int wid  = tid >> 5;
    const int lane = tid & 31;
    const int l    = blockIdx.x / TPL;
    const int n0   = (blockIdx.x % TPL) * NT;

    uint32_t smb = smem_u32(dynsm);
    smb = (smb + 1023u) & ~1023u;
    const uint32_t cm0 = smem_u32(&cmbar[0]);
    const uint32_t fm0 = smem_u32(&fmbar[0]);

    if (wid == 0) tc_alloc(smem_u32(&tmem_ptr_sm), 512);
    if (tid == 0) {
        MBARRIER_INIT(cm0 + 0, 1);  MBARRIER_INIT(cm0 + 8, 1);
        MBARRIER_INIT(fm0 + 0, 1);  MBARRIER_INIT(fm0 + 8, 1);
    }
    if (tid < NT)
        bias_sm[tid] = __ldg(&bih[l * HID + n0 + tid]) + __ldg(&bhh[l * HID + n0 + tid]);
    __syncthreads();
    const uint32_t tmem = tmem_ptr_sm;
    if (wid == 0) tc_relinquish();

    unsigned pc0 = 0, pc1 = 0;     // producer: commit phases consumed
    unsigned ic0 = 0, ic1 = 0;     // issuer: full phases consumed

    for (int s = 0; s < S_LEN + NLAYER - 1; s++) {
        if (s > 0) grid_barrier();
        const int t = s - l;
        if (t < 0 || t >= S_LEN) continue;
        const int pp = (s + 1) & 1;

        if (wid == 8) {
            // ============ PRODUCER WARP: TMA per chunk ============
            #pragma unroll 1
            for (int ch = 0; ch < NCHUNK; ch++) {
                const int b = ch & 1;
                if (ch >= 2) {                   // slot reuse: MMAs of ch-2 done
                    if (b == 0) { MBAR_WAIT(cm0 + 0, pc0 & 1); pc0++; }
                    else        { MBAR_WAIT(cm0 + 8, pc1 & 1); pc1++; }
                }
                if (lane == 0) {
                    const uint32_t bb = smb + (uint32_t)b * SLOTSZ;
                    const uint32_t fb = (b == 0) ? fm0 : fm0 + 8;
                    const int g  = ch >> 4;
                    const int k0 = (ch & 15) * KC;
                    MBARRIER_EXPECT_TX(fb, SLOTSZ);
                    // A source: x (l==0, g==0) else h[l-1] (g==0) / h[l] (g==1)
                    if (g == 0 && l == 0) {
                        int ar = t * BATCH;
                        TMA_LOAD_2D(bb + OFF_AHI, &mxh, k0, ar, fb);
                        TMA_LOAD_2D(bb + OFF_ALO, &mxl, k0, ar, fb);
                    } else {
                        int ls = g ? l : (l - 1);
                        int ar = (pp * NLAYER + ls) * BATCH;
                        TMA_LOAD_2D(bb + OFF_AHI, &mhh, k0, ar, fb);
                        TMA_LOAD_2D(bb + OFF_ALO, &mhl, k0, ar, fb);
                    }
                    int wr = (g * NLAYER + l) * HID + n0;
                    TMA_LOAD_2D(bb + OFF_WHI, &mwh, k0, wr, fb);
                    TMA_LOAD_2D(bb + OFF_WLO, &mwl, k0, wr, fb);
                }
            }
            // final commits of this step (chunks 30/31)
            MBAR_WAIT(cm0 + 0, pc0 & 1); pc0++;
            MBAR_WAIT(cm0 + 8, pc1 & 1); pc1++;
        } else if (wid == 9) {
            // ============ ISSUER WARP: MMA per chunk ============
            TC_FENCE_AFTER();                    // order prev-step LDTM vs MMA
            #pragma unroll 1
            for (int ch = 0; ch < NCHUNK; ch++) {
                const int b = ch & 1;
                if (b == 0) { MBAR_WAIT(fm0 + 0, ic0 & 1); ic0++; }
                else        { MBAR_WAIT(fm0 + 8, ic1 & 1); ic1++; }
                if (lane == 0) {
                    const uint32_t bb = smb + (uint32_t)b * SLOTSZ;
                    #pragma unroll
                    for (int mh = 0; mh < 2; mh++) {
                        #pragma unroll
                        for (int ps = 0; ps < 3; ps++) {
                            // ps0: Ahi*Whi  ps1: Ahi*Wlo  ps2: Alo*Whi
                            uint64_t ad = mkdesc(bb + (ps == 2 ? OFF_ALO : OFF_AHI)
                                                 + (uint32_t)mh * 16384u);
                            uint64_t bd = mkdesc(bb + (ps == 1 ? OFF_WLO : OFF_WHI));
                            #pragma unroll
                            for (int ks = 0; ks < 4; ks++) {
                                uint32_t en = !(ch == 0 && ps == 0 && ks == 0);
                                tc_mma_ss(tmem + TM_D + mh * 64, ad + ks * 2,
                                          bd + ks * 2, IDESC, en);
                            }
                        }
                    }
                    tc_commit(b == 0 ? cm0 : cm0 + 8);
                }
            }
        }
        // producer has waited the final commits; sync everyone before LDTM
        __syncthreads();

        // ---- epilogue (warps 0-7): LDTM -> +bias -> tanh -> split/store ----
        if (wid < 8) {
            TC_FENCE_AFTER();
            const int mh  = wid >> 2;
            const int row = mh * 128 + (wid & 3) * 32 + lane;
            const int wp  = s & 1;

            #pragma unroll
            for (int hf = 0; hf < 2; hf++) {
                uint32_t r[32];
                LDTM_X32(r, tmem + TM_D + mh * 64 + hf * 32);
                TC_WAIT_LD();

                float hv[32];
                #pragma unroll
                for (int c = 0; c < 32; c++)
                    hv[c] = tanhf(__uint_as_float(r[c]) + bias_sm[hf * 32 + c]);

                uint32_t hip[16], lop[16];
                #pragma unroll
                for (int c = 0; c < 32; c += 2)
                    split2(hv[c], hv[c + 1], hip[c >> 1], lop[c >> 1]);

                uint4* dh = (uint4*)&g_h_hi[wp][l][row][n0 + hf * 32];
                uint4* dl = (uint4*)&g_h_lo[wp][l][row][n0 + hf * 32];
                #pragma unroll
                for (int q = 0; q < 4; q++) {
                    dh[q] = make_uint4(hip[4*q], hip[4*q+1], hip[4*q+2], hip[4*q+3]);
                    dl[q] = make_uint4(lop[4*q], lop[4*q+1], lop[4*q+2], lop[4*q+3]);
                }
                if (l == NLAYER - 1) {
                    float4* yb = (float4*)(out + (size_t)t * BH
                                           + (size_t)row * HID + n0 + hf * 32);
                    #pragma unroll
                    for (int q = 0; q < 8; q++)
                        yb[q] = make_float4(hv[4*q], hv[4*q+1], hv[4*q+2], hv[4*q+3]);
                }
                if (t == S_LEN - 1) {
                    float4* hb = (float4*)(out + Y_ELEMS + (size_t)l * BH
                                           + (size_t)row * HID + n0 + hf * 32);
                    #pragma unroll
                    for (int q = 0; q < 8; q++)
                        hb[q] = make_float4(hv[4*q], hv[4*q+1], hv[4*q+2], hv[4*q+3]);
                }
            }
            TC_FENCE_BEFORE();
        }
    }

    __syncthreads();
    if (wid == 0) tc_dealloc(tmem, 512);

#else
    // ================= SIMT fp32x2 fallback (base sm_103 pass) =================
    extern __shared__ __align__(16) char dynsm[];
    float (*At)[FB_ASTR] = (float(*)[FB_ASTR])dynsm;
    float (*Wt)[FB_WSTR] = (float(*)[FB_WSTR])(dynsm + sizeof(float) * BATCH * FB_ASTR);

    const int tid = threadIdx.x;
    const int ty  = tid >> 2;
    const int tx  = tid & 3;
    const int l   = blockIdx.x / TPL;
    const int nb  = (blockIdx.x % TPL) * NT;

    const float* Wl_ih = Wih + (size_t)l * HID * HID;
    const float* Wl_hh = Whh + (size_t)l * HID * HID;

    for (int s = 0; s < S_LEN + NLAYER - 1; s++) {
        if (s > 0) grid_barrier();
        int t = s - l;
        if (t < 0 || t >= S_LEN) continue;

        const float* A0 = (l == 0) ? (x + (size_t)t * BH) : &g_hf[(s + 1) & 1][l - 1][0][0];
        const float* A1 = (t == 0) ? (h0 + (size_t)l * BH) : &g_hf[(s + 1) & 1][l][0][0];

        for (int st = 0; st < NT / 16; st++) {
            const int n0 = nb + st * 16;
            float bias[4];
            #pragma unroll
            for (int j = 0; j < 4; j++) {
                int c = n0 + tx * 4 + j;
                bias[j] = __ldg(&bih[l * HID + c]) + __ldg(&bhh[l * HID + c]);
            }
            unsigned long long acc[4][2];
            #pragma unroll
            for (int ri = 0; ri < 4; ri++) {
                acc[ri][0] = pack2(bias[0], bias[1]);
                acc[ri][1] = pack2(bias[2], bias[3]);
            }
            simt_gemm(A0, Wl_ih, n0, tid, ty, tx, acc, At, Wt);
            simt_gemm(A1, Wl_hh, n0, tid, ty, tx, acc, At, Wt);

            if (tid < 256) {
                float* hb = &g_hf[s & 1][l][0][0];
                #pragma unroll
                for (int ri = 0; ri < 4; ri++) {
                    float2 v0 = unpack2(acc[ri][0]);
                    float2 v1 = unpack2(acc[ri][1]);
                    float4 h;
                    h.x = tanhf(v0.x); h.y = tanhf(v0.y);
                    h.z = tanhf(v1.x); h.w = tanhf(v1.y);
                    int row = ty + 64 * ri;
                    size_t off = (size_t)row * HID + n0 + tx * 4;
                    *(float4*)(hb + off) = h;
                    if (l == NLAYER - 1)
                        *(float4*)(out + (size_t)t * BH + off) = h;
                    if (t == S_LEN - 1)
                        *(float4*)(out + Y_ELEMS + (size_t)l * BH + off) = h;
                }
            }
        }
    }
#endif
}

// ---------------- host: tensormap construction + launch ----------------
typedef CUresult (*PFN_encodeTiled)(
    CUtensorMap*, CUtensorMapDataType, cuuint32_t, void*,
    const cuuint64_t*, const cuuint64_t*, const cuuint32_t*, const cuuint32_t*,
    CUtensorMapInterleave, CUtensorMapSwizzle, CUtensorMapL2promotion,
    CUtensorMapFloatOOBfill);

static void make_map2d(PFN_encodeTiled enc, CUtensorMap* m, void* base,
                       unsigned long long rows, unsigned box_rows) {
    cuuint64_t dims[2]    = {HID, rows};
    cuuint64_t strides[1] = {HID * sizeof(__nv_bfloat16)};
    cuuint32_t box[2]     = {KC, box_rows};     // 64 elems x 2B = 128B (SW128)
    cuuint32_t es[2]      = {1, 1};
    enc(m, CU_TENSOR_MAP_DATA_TYPE_BFLOAT16, 2, base, dims, strides, box, es,
        CU_TENSOR_MAP_INTERLEAVE_NONE, CU_TENSOR_MAP_SWIZZLE_128B,
        CU_TENSOR_MAP_L2_PROMOTION_L2_128B, CU_TENSOR_MAP_FLOAT_OOB_FILL_NONE);
}

extern "C" void kernel_launch(void* const* d_in, const int* in_sizes, int n_in,
                              void* d_out, int out_size) {
    const float* x   = (const float*)d_in[0];
    const float* h0  = (const float*)d_in[1];
    const float* Wih = (const float*)d_in[2];
    const float* Whh = (const float*)d_in[3];
    const float* bih = (const float*)d_in[4];
    const float* bhh = (const float*)d_in[5];

    cudaFuncSetAttribute(rnn_tc, cudaFuncAttributeMaxDynamicSharedMemorySize, SMEM_DYN);

    // Resolve driver tensormap encoder through the runtime (no -lcuda needed).
    void* fn = nullptr;
    cudaDriverEntryPointQueryResult qr;
    cudaGetDriverEntryPoint("cuTensorMapEncodeTiled", &fn,
                            cudaEnableDefault, &qr);
    PFN_encodeTiled enc = (PFN_encodeTiled)fn;

    void *pxh, *pxl, *phh, *phl, *pwh, *pwl;
    cudaGetSymbolAddress(&pxh, g_x_hi);
    cudaGetSymbolAddress(&pxl, g_x_lo);
    cudaGetSymbolAddress(&phh, g_h_hi);
    cudaGetSymbolAddress(&phl, g_h_lo);
    cudaGetSymbolAddress(&pwh, g_w_hi);
    cudaGetSymbolAddress(&pwl, g_w_lo);

    CUtensorMap mxh, mxl, mhh, mhl, mwh, mwl;
    make_map2d(enc, &mxh, pxh, (unsigned long long)S_LEN * BATCH, BATCH);
    make_map2d(enc, &mxl, pxl, (unsigned long long)S_LEN * BATCH, BATCH);
    make_map2d(enc, &mhh, phh, 2ull * NLAYER * BATCH, BATCH);
    make_map2d(enc, &mhl, phl, 2ull * NLAYER * BATCH, BATCH);
    make_map2d(enc, &mwh, pwh, 2ull * NLAYER * HID, NT);
    make_map2d(enc, &mwl, pwl, 2ull * NLAYER * HID, NT);

    size_t tot4 = (size_t)NLAYER * HID * HID / 4;
    split_weights<<<(unsigned)((tot4 + 255) / 256), 256>>>(Wih, Whh);
    split_x<<<4096, 256>>>(x);
    size_t h4 = (size_t)NLAYER * BH / 4;
    seed_h0<<<(unsigned)((h4 + 255) / 256), 256>>>(h0);
    rnn_tc<<<NCTA, NTHREADS, SMEM_DYN>>>(mxh, mxl, mhh, mhl, mwh, mwl,
                                         x, h0, Wih, Whh, bih, bhh, (float*)d_out);
}

// round 17
// speedup vs baseline: 3.7770x; 1.9807x over previous
#include <cuda_runtime.h>
#include <cuda.h>
#include <cuda_bf16.h>
#include <cstdint>
#include <cstddef>

// MinimalRNN 3-layer tanh RNN, S=256, B=256, H=1024.
// Persistent kernel, skewed layer pipeline (layer l computes t = s - l).
// sm_103a pass: tcgen05 bf16 3-pass (hi/lo split), SS mode, TMA staging.
// R17: re-tile M=128 x N=128 per CTA (48 CTAs = 3 layers x 8 n-tiles x 2
// M-halves). N=128 makes each MMA crossbar-fit (8KB/64cyc = 125 B/cyc vs
// 128 B/cyc) and halves A-traffic per output — R16 was SMEM-bandwidth-bound
// (N=64: 187 B/cyc demand). 12 MMAs/chunk at the 64-cyc floor.

#if defined(__CUDA_ARCH_FEAT_SM103_ALL) || defined(__CUDA_ARCH_FEAT_SM100_ALL) || \
    defined(__CUDA_ARCH_FEAT_SM101_ALL) || defined(__CUDA_ARCH_SPECIFIC__)
#define TC_OK 1
#endif
#if !defined(__CUDA_ARCH__) || defined(TC_OK)
#define COMPILE_TC 1          // host pass + arch-specific device pass
#endif

#define S_LEN   256
#define BATCH   256
#define HID     1024
#define NLAYER  3
#define NT      128                 // output columns per CTA
#define TPL     (HID / NT)          // 8 n-tiles per layer
#define NCTA    (NLAYER * TPL * 2)  // 48 (x2 M-halves)
#define NTHREADS 256                // warps 0-3 epilogue, 4 producer, 5 issuer
#define KC      64                  // k elems per chunk
#define NCHUNK  32                  // 2 GEMMs x 16 chunks
#define BH      ((size_t)BATCH * HID)
#define Y_ELEMS ((size_t)S_LEN * BATCH * HID)

// Stage slot layout (bytes): A hi 16K, A lo 16K, W hi 16K, W lo 16K
#define OFF_AHI 0
#define OFF_ALO 16384
#define OFF_WHI 32768
#define OFF_WLO 49152
#define SLOTSZ  65536
#define SMEM_DYN (2 * SLOTSZ + 1024)

#define TM_D    0                   // TMEM: D accumulator (128 cols)

// idesc kind::f16: dtype=F32(1<<4) atype=BF16(1<<7) btype=BF16(1<<10)
// N/8=16 (<<17), M/16=8 (<<24)
#define IDESC 0x08200490u

// ---------------- global scratch ----------------
__device__ __align__(16) __nv_bfloat16 g_w_hi[2u * NLAYER * HID * HID];
__device__ __align__(16) __nv_bfloat16 g_w_lo[2u * NLAYER * HID * HID];
__device__ __align__(16) __nv_bfloat16 g_x_hi[(size_t)S_LEN * BATCH * HID];
__device__ __align__(16) __nv_bfloat16 g_x_lo[(size_t)S_LEN * BATCH * HID];
__device__ __align__(16) __nv_bfloat16 g_h_hi[2][NLAYER][BATCH][HID];
__device__ __align__(16) __nv_bfloat16 g_h_lo[2][NLAYER][BATCH][HID];
__device__ __align__(16) float         g_hf[2][NLAYER][BATCH][HID];  // fallback
__device__ unsigned g_count = 0;
__device__ unsigned g_gen   = 0;

// ---------------- generic helpers ----------------
__device__ __forceinline__ uint32_t smem_u32(const void* p) {
    uint32_t a;
    asm("{ .reg .u64 t; cvta.to.shared.u64 t, %1; cvt.u32.u64 %0, t; }"
        : "=r"(a) : "l"(p));
    return a;
}
__device__ __forceinline__ uint64_t mkdesc(uint32_t addr) { // SW128, LBO=1, SBO=64
    return ((uint64_t)2 << 61) | ((uint64_t)1 << 46) | ((uint64_t)64 << 32)
         | ((uint64_t)1 << 16) | ((addr >> 4) & 0x3FFF);
}
__device__ __forceinline__ uint32_t pkbf(__nv_bfloat16 a, __nv_bfloat16 b) {
    __nv_bfloat162 t = __halves2bfloat162(a, b);
    return *reinterpret_cast<uint32_t*>(&t);
}
__device__ __forceinline__ void split2(float x, float y, uint32_t& h, uint32_t& l) {
    __nv_bfloat16 hx = __float2bfloat16(x), hy = __float2bfloat16(y);
    __nv_bfloat16 lx = __float2bfloat16(x - __bfloat162float(hx));
    __nv_bfloat16 ly = __float2bfloat16(y - __bfloat162float(hy));
    h = pkbf(hx, hy); l = pkbf(lx, ly);
}

// ---------------- grid barrier ----------------
__device__ __forceinline__ unsigned ld_acq(const unsigned* p) {
    unsigned v;
    asm volatile("ld.acquire.gpu.global.u32 %0, [%1];" : "=r"(v) : "l"(p) : "memory");
    return v;
}
__device__ __forceinline__ void grid_barrier() {
    __syncthreads();
    if (threadIdx.x == 0) {
        __threadfence();
        unsigned gen = ld_acq(&g_gen);
        __threadfence();
        unsigned ticket = atomicAdd(&g_count, 1u);
        if (ticket == NCTA - 1) {
            atomicExch(&g_count, 0u);
            __threadfence();
            atomicAdd(&g_gen, 1u);
        } else {
            while (ld_acq(&g_gen) == gen) { __nanosleep(64); }
        }
        __threadfence();
    }
    __syncthreads();
}

// ---------------- packed f32x2 (fallback path) ----------------
__device__ __forceinline__ void ffma2(unsigned long long& d,
                                      unsigned long long a, unsigned long long b) {
    asm volatile("fma.rn.f32x2 %0, %1, %2, %0;" : "+l"(d) : "l"(a), "l"(b));
}
__device__ __forceinline__ unsigned long long splat2(float v) {
    unsigned long long r;
    asm("mov.b64 %0, {%1, %1};" : "=l"(r) : "f"(v));
    return r;
}
__device__ __forceinline__ unsigned long long pack2(float a, float b) {
    unsigned long long r;
    asm("mov.b64 %0, {%1, %2};" : "=l"(r) : "f"(a), "f"(b));
    return r;
}
__device__ __forceinline__ float2 unpack2(unsigned long long v) {
    float2 f;
    asm("mov.b64 {%0, %1}, %2;" : "=f"(f.x), "=f"(f.y) : "l"(v));
    return f;
}

#define FB_KC   32
#define FB_ASTR 36
#define FB_WSTR 20
__device__ __forceinline__ void simt_gemm(
    const float* __restrict__ A, const float* __restrict__ W,
    int n0, int tid, int ty, int tx,
    unsigned long long acc[4][2],
    float (*At)[FB_ASTR], float (*Wt)[FB_WSTR])
{
    const int arow = tid >> 3, aq = tid & 7;
    const int wc = tid & 15, wq = tid >> 4;
    for (int kc = 0; kc < HID; kc += FB_KC) {
        #pragma unroll
        for (int it = 0; it < 8; it++) {
            int row = arow + 32 * it;
            float4 v = __ldcg((const float4*)(A + (size_t)row * HID + kc + aq * 4));
            *(float4*)&At[row][aq * 4] = v;
        }
        if (tid < 128) {
            float4 wv = __ldg((const float4*)(W + (size_t)(n0 + wc) * HID + kc + wq * 4));
            Wt[wq * 4 + 0][wc] = wv.x; Wt[wq * 4 + 1][wc] = wv.y;
            Wt[wq * 4 + 2][wc] = wv.z; Wt[wq * 4 + 3][wc] = wv.w;
        }
        __syncthreads();
        #pragma unroll
        for (int k4 = 0; k4 < FB_KC; k4 += 4) {
            ulonglong2 wp[4];
            #pragma unroll
            for (int j = 0; j < 4; j++)
                wp[j] = *(const ulonglong2*)&Wt[k4 + j][tx * 4];
            float4 av[4];
            #pragma unroll
            for (int ri = 0; ri < 4; ri++)
                av[ri] = *(const float4*)&At[ty + 64 * ri][k4];
            #pragma unroll
            for (int j = 0; j < 4; j++) {
                #pragma unroll
                for (int ri = 0; ri < 4; ri++) {
                    unsigned long long as = splat2(((const float*)&av[ri])[j]);
                    ffma2(acc[ri][0], as, wp[j].x);
                    ffma2(acc[ri][1], as, wp[j].y);
                }
            }
        }
        __syncthreads();
    }
}

// ---------------- tcgen05 / TMA wrappers (arch-specific pass only) ----------
#if defined(COMPILE_TC)
#define MBARRIER_INIT(addr, cnt) \
    asm volatile("mbarrier.init.shared.b64 [%0], %1;" :: "r"(addr), "r"(cnt) : "memory")
#define MBARRIER_EXPECT_TX(addr, bytes) \
    asm volatile("mbarrier.arrive.expect_tx.shared.b64 _, [%0], %1;" \
                 :: "r"(addr), "r"(bytes) : "memory")
#define MBAR_WAIT(addr, parity) do {                                            \
    uint32_t _done;                                                             \
    asm volatile("{\n\t.reg .pred p;\n\t"                                       \
        "mbarrier.try_wait.parity.acquire.cta.shared::cta.b64 p, [%1], %2;\n\t" \
        "selp.b32 %0, 1, 0, p;\n\t}"                                            \
        : "=r"(_done) : "r"(addr), "r"(parity) : "memory");                     \
    if (!_done) {                                                               \
        asm volatile("{\n\t.reg .pred P1;\n\t"                                  \
            "WL_%=:\n\t"                                                        \
            "mbarrier.try_wait.parity.acquire.cta.shared::cta.b64 P1, [%0], %1, 0x989680;\n\t" \
            "@P1 bra.uni WD_%=;\n\t"                                            \
            "bra.uni WL_%=;\n\t"                                                \
            "WD_%=:\n\t}" :: "r"(addr), "r"(parity) : "memory");                \
    }                                                                           \
} while (0)

#define TMA_LOAD_2D(smem, map, cx, cy, mbar)                                    \
    asm volatile("cp.async.bulk.tensor.2d.shared::cta.global.tile"              \
        ".mbarrier::complete_tx::bytes [%0], [%1, {%2, %3}], [%4];"             \
        :: "r"(smem), "l"(map), "r"(cx), "r"(cy), "r"(mbar) : "memory")

__device__ __forceinline__ void tc_alloc(uint32_t dst_smem, uint32_t ncols) {
    asm volatile("tcgen05.alloc.cta_group::1.sync.aligned.shared::cta.b32 [%0], %1;"
                 :: "r"(dst_smem), "r"(ncols) : "memory");
}
__device__ __forceinline__ void tc_dealloc(uint32_t tmem, uint32_t ncols) {
    asm volatile("tcgen05.dealloc.cta_group::1.sync.aligned.b32 %0, %1;"
                 :: "r"(tmem), "r"(ncols));
}
__device__ __forceinline__ void tc_relinquish() {
    asm volatile("tcgen05.relinquish_alloc_permit.cta_group::1.sync.aligned;");
}
__device__ __forceinline__ void tc_mma_ss(uint32_t d, uint64_t ad, uint64_t bd,
                                          uint32_t idesc, uint32_t en) {
    asm volatile("{\n\t.reg .pred p;\n\tsetp.ne.u32 p, %5, 0;\n\t"
        "tcgen05.mma.cta_group::1.kind::f16 [%0], %1, %2, %3, {%4,%4,%4,%4}, p;\n\t}"
        :: "r"(d), "l"(ad), "l"(bd), "r"(idesc), "r"(0u), "r"(en) : "memory");
}
__device__ __forceinline__ void tc_commit(uint32_t mbar) {
    asm volatile("tcgen05.commit.cta_group::1.mbarrier::arrive::one.shared::cluster.b64 [%0];"
                 :: "r"(mbar) : "memory");
}
#define TC_FENCE_BEFORE() asm volatile("tcgen05.fence::before_thread_sync;" ::: "memory")
#define TC_FENCE_AFTER()  asm volatile("tcgen05.fence::after_thread_sync;"  ::: "memory")
#define TC_WAIT_LD()      asm volatile("tcgen05.wait::ld.sync.aligned;" ::: "memory")

#define LDTM_X32(r, a)                                                          \
    asm volatile("tcgen05.ld.sync.aligned.32x32b.x32.b32 "                      \
        "{%0,%1,%2,%3,%4,%5,%6,%7,%8,%9,%10,%11,%12,%13,%14,%15,"               \
        "%16,%17,%18,%19,%20,%21,%22,%23,%24,%25,%26,%27,%28,%29,%30,%31}, [%32];" \
        : "=r"((r)[0]),"=r"((r)[1]),"=r"((r)[2]),"=r"((r)[3]),                  \
          "=r"((r)[4]),"=r"((r)[5]),"=r"((r)[6]),"=r"((r)[7]),                  \
          "=r"((r)[8]),"=r"((r)[9]),"=r"((r)[10]),"=r"((r)[11]),                \
          "=r"((r)[12]),"=r"((r)[13]),"=r"((r)[14]),"=r"((r)[15]),              \
          "=r"((r)[16]),"=r"((r)[17]),"=r"((r)[18]),"=r"((r)[19]),              \
          "=r"((r)[20]),"=r"((r)[21]),"=r"((r)[22]),"=r"((r)[23]),              \
          "=r"((r)[24]),"=r"((r)[25]),"=r"((r)[26]),"=r"((r)[27]),              \
          "=r"((r)[28]),"=r"((r)[29]),"=r"((r)[30]),"=r"((r)[31])               \
        : "r"(a))
#endif // COMPILE_TC

// ---------------- prelude kernels ----------------
extern "C" __global__ void split_weights(const float* __restrict__ Wih,
                                         const float* __restrict__ Whh) {
    size_t tot4 = (size_t)NLAYER * HID * HID / 4;
    size_t i4 = (size_t)blockIdx.x * blockDim.x + threadIdx.x;
    if (i4 >= tot4) return;
    float4 a = __ldg((const float4*)Wih + i4);
    float4 b = __ldg((const float4*)Whh + i4);
    uint2 h, l;
    split2(a.x, a.y, h.x, l.x); split2(a.z, a.w, h.y, l.y);
    ((uint2*)g_w_hi)[i4] = h;  ((uint2*)g_w_lo)[i4] = l;
    split2(b.x, b.y, h.x, l.x); split2(b.z, b.w, h.y, l.y);
    ((uint2*)g_w_hi)[tot4 + i4] = h;  ((uint2*)g_w_lo)[tot4 + i4] = l;
}

extern "C" __global__ void split_x(const float* __restrict__ x) {
    size_t tot4 = Y_ELEMS / 4;
    for (size_t i4 = (size_t)blockIdx.x * blockDim.x + threadIdx.x;
         i4 < tot4; i4 += (size_t)gridDim.x * blockDim.x) {
        float4 a = __ldg((const float4*)x + i4);
        uint2 h, l;
        split2(a.x, a.y, h.x, l.x); split2(a.z, a.w, h.y, l.y);
        ((uint2*)g_x_hi)[i4] = h;  ((uint2*)g_x_lo)[i4] = l;
    }
}

// seed h0 into the parity slot read at t==0 for each layer: pp = (l+1)&1
extern "C" __global__ void seed_h0(const float* __restrict__ h0) {
    size_t tot4 = (size_t)NLAYER * BH / 4;
    size_t i4 = (size_t)blockIdx.x * blockDim.x + threadIdx.x;
    if (i4 >= tot4) return;
    int l = (int)(i4 / (BH / 4));
    size_t r4 = i4 % (BH / 4);
    int pp = (l + 1) & 1;
    float4 a = __ldg((const float4*)h0 + i4);
    uint2 h, lo;
    split2(a.x, a.y, h.x, lo.x); split2(a.z, a.w, h.y, lo.y);
    ((uint2*)&g_h_hi[pp][l][0][0])[r4] = h;
    ((uint2*)&g_h_lo[pp][l][0][0])[r4] = lo;
}

// ---------------- persistent RNN kernel ----------------
extern "C" __global__ void __launch_bounds__(NTHREADS, 1)
rnn_tc(const __grid_constant__ CUtensorMap mxh,  // g_x_hi  [65536 x 1024]
       const __grid_constant__ CUtensorMap mxl,  // g_x_lo
       const __grid_constant__ CUtensorMap mhh,  // g_h_hi  [1536 x 1024]
       const __grid_constant__ CUtensorMap mhl,  // g_h_lo
       const __grid_constant__ CUtensorMap mwh,  // g_w_hi  [6144 x 1024]
       const __grid_constant__ CUtensorMap mwl,  // g_w_lo
       const float* __restrict__ x,    // fallback only
       const float* __restrict__ h0,   // fallback only
       const float* __restrict__ Wih,  // fallback only
       const float* __restrict__ Whh,  // fallback only
       const float* __restrict__ bih,  // [L][H]
       const float* __restrict__ bhh,  // [L][H]
       float* __restrict__ out)        // y [S*B*H] ++ h_N [L*B*H]
{
#if defined(COMPILE_TC)
    // ========== tcgen05 SS + TMA, M=128 x N=128 per CTA ==========
    (void)x; (void)h0; (void)Wih; (void)Whh;
    extern __shared__ __align__(1024) char dynsm[];
    __shared__ __align__(16) uint64_t cmbar[2];   // MMA commit per slot
    __shared__ __align__(16) uint64_t fmbar[2];   // TMA full per slot
    __shared__ uint32_t tmem_ptr_sm;
    __shared__ float bias_sm[NT];

    const int tid  = threadIdx.x;
    const int wid  = tid >> 5;
    const int lane = tid & 31;
    // blockIdx -> (layer, n-tile, m-half)
    const int l    = blockIdx.x / (TPL * 2);
    const int rem  = blockIdx.x % (TPL * 2);
    const int n0   = (rem >> 1) * NT;
    const int mh   = rem & 1;                     // batch rows mh*128..+127

    uint32_t smb = smem_u32(dynsm);
    smb = (smb + 1023u) & ~1023u;
    const uint32_t cm0 = smem_u32(&cmbar[0]);
    const uint32_t fm0 = smem_u32(&fmbar[0]);

    if (wid == 0) tc_alloc(smem_u32(&tmem_ptr_sm), 128);
    if (tid == 0) {
        MBARRIER_INIT(cm0 + 0, 1);  MBARRIER_INIT(cm0 + 8, 1);
        MBARRIER_INIT(fm0 + 0, 1);  MBARRIER_INIT(fm0 + 8, 1);
    }
    if (tid < NT)
        bias_sm[tid] = __ldg(&bih[l * HID + n0 + tid]) + __ldg(&bhh[l * HID + n0 + tid]);
    __syncthreads();
    const uint32_t tmem = tmem_ptr_sm;
    if (wid == 0) tc_relinquish();

    unsigned pc0 = 0, pc1 = 0;     // producer: commit phases consumed
    unsigned ic0 = 0, ic1 = 0;     // issuer: full phases consumed

    for (int s = 0; s < S_LEN + NLAYER - 1; s++) {
        if (s > 0) grid_barrier();
        const int t = s - l;
        if (t < 0 || t >= S_LEN) continue;
        const int pp = (s + 1) & 1;

        if (wid == 4) {
            // ============ PRODUCER WARP: TMA per chunk ============
            #pragma unroll 1
            for (int ch = 0; ch < NCHUNK; ch++) {
                const int b = ch & 1;
                if (ch >= 2) {                   // slot reuse: MMAs of ch-2 done
                    if (b == 0) { MBAR_WAIT(cm0 + 0, pc0 & 1); pc0++; }
                    else        { MBAR_WAIT(cm0 + 8, pc1 & 1); pc1++; }
                }
                if (lane == 0) {
                    const uint32_t bb = smb + (uint32_t)b * SLOTSZ;
                    const uint32_t fb = (b == 0) ? fm0 : fm0 + 8;
                    const int g  = ch >> 4;
                    const int k0 = (ch & 15) * KC;
                    MBARRIER_EXPECT_TX(fb, SLOTSZ);
                    if (g == 0 && l == 0) {
                        int ar = t * BATCH + mh * 128;
                        TMA_LOAD_2D(bb + OFF_AHI, &mxh, k0, ar, fb);
                        TMA_LOAD_2D(bb + OFF_ALO, &mxl, k0, ar, fb);
                    } else {
                        int ls = g ? l : (l - 1);
                        int ar = (pp * NLAYER + ls) * BATCH + mh * 128;
                        TMA_LOAD_2D(bb + OFF_AHI, &mhh, k0, ar, fb);
                        TMA_LOAD_2D(bb + OFF_ALO, &mhl, k0, ar, fb);
                    }
                    int wr = (g * NLAYER + l) * HID + n0;
                    TMA_LOAD_2D(bb + OFF_WHI, &mwh, k0, wr, fb);
                    TMA_LOAD_2D(bb + OFF_WLO, &mwl, k0, wr, fb);
                }
            }
            // final commits of this step (chunks 30/31)
            MBAR_WAIT(cm0 + 0, pc0 & 1); pc0++;
            MBAR_WAIT(cm0 + 8, pc1 & 1); pc1++;
        } else if (wid == 5) {
            // ============ ISSUER WARP: MMA per chunk ============
            TC_FENCE_AFTER();                    // order prev-step LDTM vs MMA
            #pragma unroll 1
            for (int ch = 0; ch < NCHUNK; ch++) {
                const int b = ch & 1;
                if (b == 0) { MBAR_WAIT(fm0 + 0, ic0 & 1); ic0++; }
                else        { MBAR_WAIT(fm0 + 8, ic1 & 1); ic1++; }
                if (lane == 0) {
                    const uint32_t bb = smb + (uint32_t)b * SLOTSZ;
                    #pragma unroll
                    for (int ps = 0; ps < 3; ps++) {
                        // ps0: Ahi*Whi  ps1: Ahi*Wlo  ps2: Alo*Whi
                        uint64_t ad = mkdesc(bb + (ps == 2 ? OFF_ALO : OFF_AHI));
                        uint64_t bd = mkdesc(bb + (ps == 1 ? OFF_WLO : OFF_WHI));
                        #pragma unroll
                        for (int ks = 0; ks < 4; ks++) {
                            uint32_t en = !(ch == 0 && ps == 0 && ks == 0);
                            tc_mma_ss(tmem + TM_D, ad + ks * 2,
                                      bd + ks * 2, IDESC, en);
                        }
                    }
                    tc_commit(b == 0 ? cm0 : cm0 + 8);
                }
            }
        }
        // producer has waited the final commits; sync all before LDTM
        __syncthreads();

        // ---- epilogue (warps 0-3): LDTM -> +bias -> tanh -> split/store ----
        if (wid < 4) {
            TC_FENCE_AFTER();
            const int row = mh * 128 + wid * 32 + lane;   // global batch row
            const int wp  = s & 1;

            #pragma unroll
            for (int cg = 0; cg < 4; cg++) {              // 4 col-groups of 32
                uint32_t r[32];
                LDTM_X32(r, tmem + TM_D + cg * 32);
                TC_WAIT_LD();

                float hv[32];
                #pragma unroll
                for (int c = 0; c < 32; c++)
                    hv[c] = tanhf(__uint_as_float(r[c]) + bias_sm[cg * 32 + c]);

                uint32_t hip[16], lop[16];
                #pragma unroll
                for (int c = 0; c < 32; c += 2)
                    split2(hv[c], hv[c + 1], hip[c >> 1], lop[c >> 1]);

                uint4* dh = (uint4*)&g_h_hi[wp][l][row][n0 + cg * 32];
                uint4* dl = (uint4*)&g_h_lo[wp][l][row][n0 + cg * 32];
                #pragma unroll
                for (int q = 0; q < 4; q++) {
                    dh[q] = make_uint4(hip[4*q], hip[4*q+1], hip[4*q+2], hip[4*q+3]);
                    dl[q] = make_uint4(lop[4*q], lop[4*q+1], lop[4*q+2], lop[4*q+3]);
                }
                if (l == NLAYER - 1) {
                    float4* yb = (float4*)(out + (size_t)t * BH
                                           + (size_t)row * HID + n0 + cg * 32);
                    #pragma unroll
                    for (int q = 0; q < 8; q++)
                        yb[q] = make_float4(hv[4*q], hv[4*q+1], hv[4*q+2], hv[4*q+3]);
                }
                if (t == S_LEN - 1) {
                    float4* hb = (float4*)(out + Y_ELEMS + (size_t)l * BH
                                           + (size_t)row * HID + n0 + cg * 32);
                    #pragma unroll
                    for (int q = 0; q < 8; q++)
                        hb[q] = make_float4(hv[4*q], hv[4*q+1], hv[4*q+2], hv[4*q+3]);
                }
            }
            TC_FENCE_BEFORE();
        }
    }

    __syncthreads();
    if (wid == 0) tc_dealloc(tmem, 128);

#else
    // ================= SIMT fp32x2 fallback (base sm_103 pass) =================
    extern __shared__ __align__(16) char dynsm[];
    float (*At)[FB_ASTR] = (float(*)[FB_ASTR])dynsm;
    float (*Wt)[FB_WSTR] = (float(*)[FB_WSTR])(dynsm + sizeof(float) * BATCH * FB_ASTR);

    const int tid = threadIdx.x;
    const int ty  = tid >> 2;
    const int tx  = tid & 3;
    const int l   = blockIdx.x / (TPL * 2);
    const int rem = blockIdx.x % (TPL * 2);
    const int nb  = (rem >> 1) * NT + (rem & 1) * (NT / 2);  // 64-col span

    const float* Wl_ih = Wih + (size_t)l * HID * HID;
    const float* Wl_hh = Whh + (size_t)l * HID * HID;

    for (int s = 0; s < S_LEN + NLAYER - 1; s++) {
        if (s > 0) grid_barrier();
        int t = s - l;
        if (t < 0 || t >= S_LEN) continue;

        const float* A0 = (l == 0) ? (x + (size_t)t * BH) : &g_hf[(s + 1) & 1][l - 1][0][0];
        const float* A1 = (t == 0) ? (h0 + (size_t)l * BH) : &g_hf[(s + 1) & 1][l][0][0];

        for (int st = 0; st < 4; st++) {
            const int n0 = nb + st * 16;
            float bias[4];
            #pragma unroll
            for (int j = 0; j < 4; j++) {
                int c = n0 + tx * 4 + j;
                bias[j] = __ldg(&bih[l * HID + c]) + __ldg(&bhh[l * HID + c]);
            }
            unsigned long long acc[4][2];
            #pragma unroll
            for (int ri = 0; ri < 4; ri++) {
                acc[ri][0] = pack2(bias[0], bias[1]);
                acc[ri][1] = pack2(bias[2], bias[3]);
            }
            simt_gemm(A0, Wl_ih, n0, tid, ty, tx, acc, At, Wt);
            simt_gemm(A1, Wl_hh, n0, tid, ty, tx, acc, At, Wt);

            float* hb = &g_hf[s & 1][l][0][0];
            #pragma unroll
            for (int ri = 0; ri < 4; ri++) {
                float2 v0 = unpack2(acc[ri][0]);
                float2 v1 = unpack2(acc[ri][1]);
                float4 h;
                h.x = tanhf(v0.x); h.y = tanhf(v0.y);
                h.z = tanhf(v1.x); h.w = tanhf(v1.y);
                int row = ty + 64 * ri;
                size_t off = (size_t)row * HID + n0 + tx * 4;
                *(float4*)(hb + off) = h;
                if (l == NLAYER - 1)
                    *(float4*)(out + (size_t)t * BH + off) = h;
                if (t == S_LEN - 1)
                    *(float4*)(out + Y_ELEMS + (size_t)l * BH + off) = h;
            }
        }
    }
#endif
}

// ---------------- host: tensormap construction + launch ----------------
typedef CUresult (*PFN_encodeTiled)(
    CUtensorMap*, CUtensorMapDataType, cuuint32_t, void*,
    const cuuint64_t*, const cuuint64_t*, const cuuint32_t*, const cuuint32_t*,
    CUtensorMapInterleave, CUtensorMapSwizzle, CUtensorMapL2promotion,
    CUtensorMapFloatOOBfill);

static void make_map2d(PFN_encodeTiled enc, CUtensorMap* m, void* base,
                       unsigned long long rows, unsigned box_rows) {
    cuuint64_t dims[2]    = {HID, rows};
    cuuint64_t strides[1] = {HID * sizeof(__nv_bfloat16)};
    cuuint32_t box[2]     = {KC, box_rows};     // 64 elems x 2B = 128B (SW128)
    cuuint32_t es[2]      = {1, 1};
    enc(m, CU_TENSOR_MAP_DATA_TYPE_BFLOAT16, 2, base, dims, strides, box, es,
        CU_TENSOR_MAP_INTERLEAVE_NONE, CU_TENSOR_MAP_SWIZZLE_128B,
        CU_TENSOR_MAP_L2_PROMOTION_L2_128B, CU_TENSOR_MAP_FLOAT_OOB_FILL_NONE);
}

extern "C" void kernel_launch(void* const* d_in, const int* in_sizes, int n_in,
                              void* d_out, int out_size) {
    const float* x   = (const float*)d_in[0];
    const float* h0  = (const float*)d_in[1];
    const float* Wih = (const float*)d_in[2];
    const float* Whh = (const float*)d_in[3];
    const float* bih = (const float*)d_in[4];
    const float* bhh = (const float*)d_in[5];

    cudaFuncSetAttribute(rnn_tc, cudaFuncAttributeMaxDynamicSharedMemorySize, SMEM_DYN);

    void* fn = nullptr;
    cudaDriverEntryPointQueryResult qr;
    cudaGetDriverEntryPoint("cuTensorMapEncodeTiled", &fn,
                            cudaEnableDefault, &qr);
    PFN_encodeTiled enc = (PFN_encodeTiled)fn;

    void *pxh, *pxl, *phh, *phl, *pwh, *pwl;
    cudaGetSymbolAddress(&pxh, g_x_hi);
    cudaGetSymbolAddress(&pxl, g_x_lo);
    cudaGetSymbolAddress(&phh, g_h_hi);
    cudaGetSymbolAddress(&phl, g_h_lo);
    cudaGetSymbolAddress(&pwh, g_w_hi);
    cudaGetSymbolAddress(&pwl, g_w_lo);

    CUtensorMap mxh, mxl, mhh, mhl, mwh, mwl;
    make_map2d(enc, &mxh, pxh, (unsigned long long)S_LEN * BATCH, 128);
    make_map2d(enc, &mxl, pxl, (unsigned long long)S_LEN * BATCH, 128);
    make_map2d(enc, &mhh, phh, 2ull * NLAYER * BATCH, 128);
    make_map2d(enc, &mhl, phl, 2ull * NLAYER * BATCH, 128);
    make_map2d(enc, &mwh, pwh, 2ull * NLAYER * HID, NT);
    make_map2d(enc, &mwl, pwl, 2ull * NLAYER * HID, NT);

    size_t tot4 = (size_t)NLAYER * HID * HID / 4;
    split_weights<<<(unsigned)((tot4 + 255) / 256), 256>>>(Wih, Whh);
    split_x<<<4096, 256>>>(x);
    size_t h4 = (size_t)NLAYER * BH / 4;
    seed_h0<<<(unsigned)((h4 + 255) / 256), 256>>>(h0);
    rnn_tc<<<NCTA, NTHREADS, SMEM_DYN>>>(mxh, mxl, mhh, mhl, mwh, mwl,
                                         x, h0, Wih, Whh, bih, bhh, (float*)d_out);
}